// round 13
// baseline (speedup 1.0000x reference)
#include <cuda_runtime.h>
#include <cuda_bf16.h>
#include <cuda_fp16.h>
#include <cstdint>

// ---------------------------------------------------------------------------
// AttentionSampling: B=4, SQ=2048, SK=8192, D=H=512, F=4, fp32.
// Round 13: single-pass fp16 GEMMs, BK=64 chunks (8 barriers instead of 16),
// 128B-row SW128 swizzle, 3-stage pipeline (96KB), 2 CTAs/SM.
// ---------------------------------------------------------------------------

#define DD 512
#define NQ  8192
#define NKV 32768
#define EPS 1e-5f

// fp32 scratch planes
#define F_Q   0
#define F_AO  (F_Q  + (size_t)NQ * DD)
#define F_O1  (F_AO + (size_t)NQ * DD)
#define F_FF  (F_O1 + (size_t)NQ * DD)
#define F_WP  (F_FF + (size_t)NQ * DD)          // w_part [NKV][16]
#define F_SW  (F_WP + (size_t)NKV * 16)         // sum-of-w [NQ]
#define F_TOT (F_SW + (size_t)NQ)
__device__ float g_scratch[F_TOT];

// fp16 activation planes
#define B_QH  0
#define B_KH  (B_QH  + (size_t)NQ  * DD)
#define B_VH  (B_KH  + (size_t)NKV * DD)        // downsampled value (NQ rows)
#define B_O1H (B_VH  + (size_t)NQ  * DD)
#define B_HH  (B_O1H + (size_t)NQ  * DD)
#define B_TOT (B_HH  + (size_t)NQ  * DD)
__device__ __half g_act[B_TOT];

// 5 weights x 512x512 fp16, stored [N][K] (transposed)
__device__ __half g_wsplit[5u * 512u * 512u];

// ---------------------------------------------------------------------------
// PTX helpers (base sm_100-legal)
// ---------------------------------------------------------------------------
__device__ __forceinline__ uint32_t smem_u32(const void* p) {
    uint32_t a;
    asm("{ .reg .u64 t; cvta.to.shared.u64 t, %1; cvt.u32.u64 %0, t; }"
        : "=r"(a) : "l"(p));
    return a;
}
__device__ __forceinline__ void ldsm_x4(uint32_t* r, uint32_t addr) {
    asm volatile("ldmatrix.sync.aligned.m8n8.x4.shared.b16 {%0,%1,%2,%3}, [%4];"
                 : "=r"(r[0]), "=r"(r[1]), "=r"(r[2]), "=r"(r[3]) : "r"(addr));
}
__device__ __forceinline__ void mma16816(float* c, const uint32_t* a, const uint32_t* b) {
    asm volatile(
        "mma.sync.aligned.m16n8k16.row.col.f32.f16.f16.f32 "
        "{%0,%1,%2,%3}, {%4,%5,%6,%7}, {%8,%9}, {%0,%1,%2,%3};"
        : "+f"(c[0]), "+f"(c[1]), "+f"(c[2]), "+f"(c[3])
        : "r"(a[0]), "r"(a[1]), "r"(a[2]), "r"(a[3]), "r"(b[0]), "r"(b[1]));
}
__device__ __forceinline__ void cp16(uint32_t saddr, const void* g) {
    asm volatile("cp.async.cg.shared.global [%0], [%1], 16;"
                 :: "r"(saddr), "l"(g) : "memory");
}
__device__ __forceinline__ void cp_commit() {
    asm volatile("cp.async.commit_group;" ::: "memory");
}

// SW128 swizzle for 128B rows: byte offset of 16B chunk (row, chunk 0..7)
__device__ __forceinline__ uint32_t swz128(uint32_t row, uint32_t chunk) {
    return row * 128u + ((chunk ^ (row & 7u)) << 4);
}

// ---------------------------------------------------------------------------
// Batched weight prep: W[k][n] fp32 -> T[n][k] fp16 (5 weights)
// ---------------------------------------------------------------------------
__global__ void prep_weight5(
    const float* w0, const float* w1, const float* w2, const float* w3, const float* w4,
    __half* base)
{
    const float* Ws[5] = {w0, w1, w2, w3, w4};
    const size_t WSZ = 512u * 512u;
    const float* W = Ws[blockIdx.z];
    __half* Th = base + (size_t)blockIdx.z * WSZ;

    __shared__ float t[32][33];
    const int bx = blockIdx.x * 32, by = blockIdx.y * 32;
    const int tx = threadIdx.x, ty = threadIdx.y; // 32 x 8
#pragma unroll
    for (int i = 0; i < 32; i += 8)
        t[ty + i][tx] = W[(size_t)(by + ty + i) * DD + bx + tx];
    __syncthreads();
#pragma unroll
    for (int i = 0; i < 32; i += 8) {
        size_t o = (size_t)(bx + ty + i) * DD + by + tx;
        Th[o] = __float2half_rn(t[tx][ty + i]);
    }
}

// ---------------------------------------------------------------------------
// fp32 -> fp16 convert (vectorized)
// ---------------------------------------------------------------------------
__global__ void __launch_bounds__(256) f32_to_h(
    const float4* __restrict__ src, uint2* __restrict__ dh)
{
    const int i = blockIdx.x * 256 + threadIdx.x;
    float4 x = src[i];
    __half2 h01, h23;
    h01.x = __float2half_rn(x.x); h01.y = __float2half_rn(x.y);
    h23.x = __float2half_rn(x.z); h23.y = __float2half_rn(x.w);
    uint2 hv;
    hv.x = *(uint32_t*)&h01; hv.y = *(uint32_t*)&h23;
    dh[i] = hv;
}

// ---------------------------------------------------------------------------
// HMMA GEMM: act(A[M,512] @ W[512,512] + bias), fp16 x fp16 -> fp32.
// BM=128, BN=128, BK=64, 256 thr (8 warps 2m x 4n; warp tile 64x32).
// 3-stage cp.async pipeline (32KB stages: Ah|Bh), SW128 swizzle,
// 1 barrier per 64-K chunk (8 total), launch_bounds(256,2) -> 2 CTAs/SM.
// DOTQ: k rows dotted with q rows instead of stored (w partials out).
// OUT_H: write fp16 plane.
// ---------------------------------------------------------------------------
#define BKC 64
#define NCH (DD / BKC)          // 8
#define PLANE 16384             // 128 rows x 128B, swizzled
#define SG_AH 0
#define SG_BH (1 * PLANE)
#define SG_SZ (2 * PLANE)       // 32768
#define STAGES 3
#define GEMM_SMEM (STAGES * SG_SZ) // 98304

template <bool RELU, bool OUT_H, bool DOTQ, bool HASBIAS>
__global__ void __launch_bounds__(256, 2) gemm_h(
    const __half* __restrict__ Ah, const __half* __restrict__ Bh,
    const float* __restrict__ bias, float* __restrict__ C,
    __half* __restrict__ Ch,
    const float* __restrict__ qdot, float* __restrict__ wpart)
{
    extern __shared__ char sm[];
    const uint32_t sb = smem_u32(sm);

    const int tid = threadIdx.x;
    const int lane = tid & 31, wid = tid >> 5;
    const int wm = (wid & 1) * 64;
    const int wn = (wid >> 1) * 32;
    const int bm = blockIdx.y * 128;
    const int bn = blockIdx.x * 128;

    float acc[4][4][4];
#pragma unroll
    for (int i = 0; i < 4; i++)
#pragma unroll
        for (int j = 0; j < 4; j++)
#pragma unroll
            for (int t = 0; t < 4; t++) acc[i][j][t] = 0.f;

    // cp.async mapping: row = tid>>1 (0..127), 4 consecutive 16B chunks
    const uint32_t lrow = (uint32_t)(tid >> 1);
    const uint32_t cbase = (uint32_t)(tid & 1) * 4;

    auto load_stage = [&](int c, int buf) {
        const uint32_t st = sb + buf * SG_SZ;
        const int kc = c * BKC;
        const __half* ga = Ah + (size_t)(bm + lrow) * DD + kc + cbase * 8;
        const __half* gb = Bh + (size_t)(bn + lrow) * DD + kc + cbase * 8;
#pragma unroll
        for (int c4 = 0; c4 < 4; c4++) {
            uint32_t so = swz128(lrow, cbase + c4);
            cp16(st + SG_AH + so, ga + c4 * 8);
            cp16(st + SG_BH + so, gb + c4 * 8);
        }
        cp_commit();
    };

    const uint32_t a_r = (uint32_t)(wm + (lane & 15));
    const uint32_t a_ch = (uint32_t)(lane >> 4);        // chunk half (0/1)
    const uint32_t b_r = (uint32_t)(wn + ((lane >> 4) << 3) + (lane & 7));
    const uint32_t b_ch = (uint32_t)((lane >> 3) & 1);

    auto compute = [&](int buf) {
        const uint32_t st = sb + buf * SG_SZ;
#pragma unroll
        for (int ks = 0; ks < 4; ks++) {
            uint32_t ah[4][4], bh[2][4];
            const uint32_t kch = (uint32_t)(ks * 2);
#pragma unroll
            for (int i = 0; i < 4; i++) {
                uint32_t off = swz128(a_r + i * 16, kch + a_ch);
                ldsm_x4(ah[i], st + SG_AH + off);
            }
#pragma unroll
            for (int jp = 0; jp < 2; jp++) {
                uint32_t off = swz128(b_r + jp * 16, kch + b_ch);
                ldsm_x4(bh[jp], st + SG_BH + off);
            }
#pragma unroll
            for (int i = 0; i < 4; i++)
#pragma unroll
                for (int j = 0; j < 4; j++)
                    mma16816(acc[i][j], ah[i], &bh[j >> 1][(j & 1) * 2]);
        }
    };

    // 3-stage pipeline, one barrier per 64-K chunk.
    load_stage(0, 0);
    load_stage(1, 1);

#pragma unroll 1
    for (int c = 0; c < NCH; c++) {
        if (c < NCH - 1)
            asm volatile("cp.async.wait_group 1;" ::: "memory");
        else
            asm volatile("cp.async.wait_group 0;" ::: "memory");
        __syncthreads();
        if (c + 2 < NCH) load_stage(c + 2, (c + 2) % 3);
        compute(c % 3);
    }

    // ---------------- epilogue ----------------
    const int crow = lane >> 2, ccol = (lane & 3) * 2;

    if (DOTQ) {
        float dotr[4][2];
#pragma unroll
        for (int i = 0; i < 4; i++) { dotr[i][0] = 0.f; dotr[i][1] = 0.f; }
#pragma unroll
        for (int i = 0; i < 4; i++) {
            const int r0 = bm + wm + i * 16 + crow;
            const float* q0p = qdot + (size_t)(r0 >> 2) * DD;
            const float* q1p = qdot + (size_t)((r0 + 8) >> 2) * DD;
#pragma unroll
            for (int j = 0; j < 4; j++) {
                const int col = bn + wn + j * 8 + ccol;
                float bx = 0.f, by = 0.f;
                if (HASBIAS) {
                    float2 bv = *(const float2*)(bias + col);
                    bx = bv.x; by = bv.y;
                }
                float k00 = fmaxf(acc[i][j][0] + bx, 0.f);
                float k01 = fmaxf(acc[i][j][1] + by, 0.f);
                float k10 = fmaxf(acc[i][j][2] + bx, 0.f);
                float k11 = fmaxf(acc[i][j][3] + by, 0.f);
                float2 q0 = *(const float2*)(q0p + col);
                float2 q1 = *(const float2*)(q1p + col);
                dotr[i][0] += k00 * q0.x + k01 * q0.y;
                dotr[i][1] += k10 * q1.x + k11 * q1.y;
            }
        }
#pragma unroll
        for (int i = 0; i < 4; i++)
#pragma unroll
            for (int p = 0; p < 2; p++) {
                float v = dotr[i][p];
                v += __shfl_xor_sync(0xffffffffu, v, 1);
                v += __shfl_xor_sync(0xffffffffu, v, 2);
                if ((lane & 3) == 0) {
                    const int row = bm + wm + i * 16 + crow + p * 8;
                    wpart[(size_t)row * 16 + blockIdx.x * 4 + (wid >> 1)] = v;
                }
            }
        return;
    }

#pragma unroll
    for (int i = 0; i < 4; i++) {
        const int r0 = bm + wm + i * 16 + crow;
#pragma unroll
        for (int j = 0; j < 4; j++) {
            const int col = bn + wn + j * 8 + ccol;
            float bx = 0.f, by = 0.f;
            if (HASBIAS) {
                float2 bv = *(const float2*)(bias + col);
                bx = bv.x; by = bv.y;
            }
            float2 o0, o1;
            o0.x = acc[i][j][0] + bx; o0.y = acc[i][j][1] + by;
            o1.x = acc[i][j][2] + bx; o1.y = acc[i][j][3] + by;
            if (RELU) {
                o0.x = fmaxf(o0.x, 0.f); o0.y = fmaxf(o0.y, 0.f);
                o1.x = fmaxf(o1.x, 0.f); o1.y = fmaxf(o1.y, 0.f);
            }
            if (OUT_H) {
                __half2 h2;
                h2.x = __float2half_rn(o0.x); h2.y = __float2half_rn(o0.y);
                *(__half2*)(Ch + (size_t)r0 * DD + col) = h2;
                h2.x = __float2half_rn(o1.x); h2.y = __float2half_rn(o1.y);
                *(__half2*)(Ch + (size_t)(r0 + 8) * DD + col) = h2;
            } else {
                *(float2*)(C + (size_t)r0 * DD + col) = o0;
                *(float2*)(C + (size_t)(r0 + 8) * DD + col) = o1;
            }
        }
    }
}

// ---------------------------------------------------------------------------
// Downsample: vds[s,:] = sum_f w[4s+f] * value[4s+f,:]; sw[s] = sum_f w.
// ---------------------------------------------------------------------------
__global__ void __launch_bounds__(256) wds_kernel(
    const float* __restrict__ wpart, const float* __restrict__ value,
    __half* __restrict__ vh, float* __restrict__ sw)
{
    const int s = blockIdx.x;
    const int tid = threadIdx.x;
    __shared__ float wp[64];
    __shared__ float wf[4];
    if (tid < 64) wp[tid] = wpart[(size_t)s * 64 + tid];
    __syncthreads();
    if (tid < 4) {
        float a = 0.f;
#pragma unroll
        for (int p = 0; p < 16; p++) a += wp[tid * 16 + p];
        wf[tid] = a;
    }
    __syncthreads();
    const float w0 = wf[0], w1 = wf[1], w2 = wf[2], w3 = wf[3];
    if (tid == 0) sw[s] = w0 + w1 + w2 + w3;

    const float* vr = value + (size_t)s * 4 * DD;
    const size_t o = (size_t)s * DD;
#pragma unroll
    for (int u = 0; u < 2; u++) {
        const int d = tid + u * 256;
        float x = w0 * vr[d] + w1 * vr[DD + d] + w2 * vr[2 * DD + d] + w3 * vr[3 * DD + d];
        vh[o + d] = __float2half_rn(x);
    }
}

// ---------------------------------------------------------------------------
// warp reduction
// ---------------------------------------------------------------------------
__device__ __forceinline__ float warp_sum(float x) {
#pragma unroll
    for (int o = 16; o > 0; o >>= 1) x += __shfl_xor_sync(0xffffffffu, x, o);
    return x;
}

// ---------------------------------------------------------------------------
// LN1: r = q + ao + sw*b_v; out1 = LN(r) (fp32 + fp16 plane)
// ---------------------------------------------------------------------------
__global__ void __launch_bounds__(256) attn_ln_kernel(
    const float* __restrict__ q, const float* __restrict__ ao,
    const float* __restrict__ sw, const float* __restrict__ bv,
    const float* __restrict__ gamma, const float* __restrict__ beta,
    float* __restrict__ out, __half* __restrict__ outh)
{
    const int row = blockIdx.x;
    const int tid = threadIdx.x;
    const int lane = tid & 31, wid = tid >> 5;
    const size_t off = (size_t)row * DD;
    const float swv = sw[row];

    float r0 = q[off + tid]       + ao[off + tid]       + swv * bv[tid];
    float r1 = q[off + tid + 256] + ao[off + tid + 256] + swv * bv[tid + 256];

    float s = warp_sum(r0 + r1);
    float ss = warp_sum(r0 * r0 + r1 * r1);
    __shared__ float rs[8], rss[8];
    if (lane == 0) { rs[wid] = s; rss[wid] = ss; }
    __syncthreads();
    __shared__ float mv[2];
    if (tid == 0) {
        float S = 0.f, SS = 0.f;
#pragma unroll
        for (int i = 0; i < 8; i++) { S += rs[i]; SS += rss[i]; }
        float mean = S * (1.f / 512.f);
        float var = SS * (1.f / 512.f) - mean * mean;
        mv[0] = mean; mv[1] = rsqrtf(var + EPS);
    }
    __syncthreads();
    const float mean = mv[0], inv = mv[1];
    float y0 = (r0 - mean) * inv * gamma[tid]       + beta[tid];
    float y1 = (r1 - mean) * inv * gamma[tid + 256] + beta[tid + 256];
    out[off + tid] = y0;
    out[off + tid + 256] = y1;
    outh[off + tid]       = __float2half_rn(y0);
    outh[off + tid + 256] = __float2half_rn(y1);
}

// ---------------------------------------------------------------------------
// Fused residual + LayerNorm2 -> output
// ---------------------------------------------------------------------------
__global__ void __launch_bounds__(256) resid_ln_kernel(
    const float* __restrict__ a, const float* __restrict__ f,
    const float* __restrict__ gamma, const float* __restrict__ beta,
    float* __restrict__ out)
{
    const int row = blockIdx.x;
    const int tid = threadIdx.x;
    const int lane = tid & 31, wid = tid >> 5;
    const size_t off = (size_t)row * DD;

    float r0 = a[off + tid]       + f[off + tid];
    float r1 = a[off + tid + 256] + f[off + tid + 256];

    float s = warp_sum(r0 + r1);
    float ss = warp_sum(r0 * r0 + r1 * r1);
    __shared__ float rs[8], rss[8];
    if (lane == 0) { rs[wid] = s; rss[wid] = ss; }
    __syncthreads();
    __shared__ float mv[2];
    if (tid == 0) {
        float S = 0.f, SS = 0.f;
#pragma unroll
        for (int i = 0; i < 8; i++) { S += rs[i]; SS += rss[i]; }
        float mean = S * (1.f / 512.f);
        float var = SS * (1.f / 512.f) - mean * mean;
        mv[0] = mean; mv[1] = rsqrtf(var + EPS);
    }
    __syncthreads();
    const float mean = mv[0], inv = mv[1];
    out[off + tid]       = (r0 - mean) * inv * gamma[tid]       + beta[tid];
    out[off + tid + 256] = (r1 - mean) * inv * gamma[tid + 256] + beta[tid + 256];
}

// ---------------------------------------------------------------------------
// Launch
// ---------------------------------------------------------------------------
extern "C" void kernel_launch(void* const* d_in, const int* in_sizes, int n_in,
                              void* d_out, int out_size)
{
    const float* query  = (const float*)d_in[0];
    const float* key    = (const float*)d_in[1];
    const float* value  = (const float*)d_in[2];
    const float* w_q    = (const float*)d_in[3];
    const float* b_q    = (const float*)d_in[4];
    const float* w_k    = (const float*)d_in[5];
    const float* b_k    = (const float*)d_in[6];
    const float* w_v    = (const float*)d_in[7];
    const float* b_v    = (const float*)d_in[8];
    const float* ln1_g  = (const float*)d_in[9];
    const float* ln1_b  = (const float*)d_in[10];
    const float* ln2_g  = (const float*)d_in[11];
    const float* ln2_b  = (const float*)d_in[12];
    const float* ffn_w1 = (const float*)d_in[13];
    const float* ffn_b1 = (const float*)d_in[14];
    const float* ffn_w2 = (const float*)d_in[15];
    const float* ffn_b2 = (const float*)d_in[16];
    float* out = (float*)d_out;

    void* sp = nullptr;
    cudaGetSymbolAddress(&sp, g_scratch);
    float* s = (float*)sp;
    float* g_q    = s + F_Q;
    float* g_ao   = s + F_AO;
    float* g_out1 = s + F_O1;
    float* g_ffn  = s + F_FF;
    float* g_wp   = s + F_WP;
    float* g_sw   = s + F_SW;

    void* ap = nullptr;
    cudaGetSymbolAddress(&ap, g_act);
    __half* a = (__half*)ap;
    __half* qh  = a + B_QH;
    __half* kh  = a + B_KH;
    __half* vh  = a + B_VH;
    __half* o1h = a + B_O1H;
    __half* hh  = a + B_HH;

    void* wp = nullptr;
    cudaGetSymbolAddress(&wp, g_wsplit);
    __half* w = (__half*)wp;
    const size_t WSZ = 512u * 512u;
    __half* wqh = w + 0 * WSZ;
    __half* wkh = w + 1 * WSZ;
    __half* wvh = w + 2 * WSZ;
    __half* f1h = w + 3 * WSZ;
    __half* f2h = w + 4 * WSZ;

    cudaFuncSetAttribute((const void*)gemm_h<true,  false, false, true >, cudaFuncAttributeMaxDynamicSharedMemorySize, GEMM_SMEM);
    cudaFuncSetAttribute((const void*)gemm_h<true,  false, true,  true >, cudaFuncAttributeMaxDynamicSharedMemorySize, GEMM_SMEM);
    cudaFuncSetAttribute((const void*)gemm_h<false, false, false, false>, cudaFuncAttributeMaxDynamicSharedMemorySize, GEMM_SMEM);
    cudaFuncSetAttribute((const void*)gemm_h<true,  true,  false, true >, cudaFuncAttributeMaxDynamicSharedMemorySize, GEMM_SMEM);
    cudaFuncSetAttribute((const void*)gemm_h<false, false, false, true >, cudaFuncAttributeMaxDynamicSharedMemorySize, GEMM_SMEM);

    const dim3 blk(256);

    prep_weight5<<<dim3(16, 16, 5), dim3(32, 8)>>>(w_q, w_k, w_v, ffn_w1, ffn_w2, w);
    f32_to_h<<<NQ  * DD / 1024, blk>>>((const float4*)query, (uint2*)qh);
    f32_to_h<<<NKV * DD / 1024, blk>>>((const float4*)key,   (uint2*)kh);

    const dim3 grid_q(DD / 128, NQ / 128);   // 4 x 64
    const dim3 grid_kv(DD / 128, NKV / 128); // 4 x 256

    // Q projection
    gemm_h<true, false, false, true><<<grid_q, blk, GEMM_SMEM>>>(
        qh, wqh, b_q, g_q, nullptr, nullptr, nullptr);

    // K projection with fused q.k dot -> w partials
    gemm_h<true, false, true, true><<<grid_kv, blk, GEMM_SMEM>>>(
        kh, wkh, b_k, nullptr, nullptr, g_q, g_wp);

    // downsample raw value by w
    wds_kernel<<<NQ, blk>>>(g_wp, value, vh, g_sw);

    // V projection on downsampled rows
    gemm_h<false, false, false, false><<<grid_q, blk, GEMM_SMEM>>>(
        vh, wvh, nullptr, g_ao, nullptr, nullptr, nullptr);

    // LN1
    attn_ln_kernel<<<NQ, blk>>>(g_q, g_ao, g_sw, b_v, ln1_g, ln1_b, g_out1, o1h);

    // FFN
    gemm_h<true, true, false, true><<<grid_q, blk, GEMM_SMEM>>>(
        o1h, f1h, ffn_b1, nullptr, hh, nullptr, nullptr);
    gemm_h<false, false, false, true><<<grid_q, blk, GEMM_SMEM>>>(
        hh, f2h, ffn_b2, g_ffn, nullptr, nullptr, nullptr);

    resid_ln_kernel<<<NQ, blk>>>(g_out1, g_ffn, ln2_g, ln2_b, out);
}

// round 14
// speedup vs baseline: 1.1104x; 1.1104x over previous
#include <cuda_runtime.h>
#include <cuda_bf16.h>
#include <cuda_fp16.h>
#include <cstdint>

// ---------------------------------------------------------------------------
// AttentionSampling: B=4, SQ=2048, SK=8192, D=H=512, F=4, fp32.
// Round 14: R12 skeleton (single-pass fp16, BK=32, 128x128, XOR swizzle,
// 1 barrier/chunk, 2 CTAs/SM) + 5-stage pipeline (80KB) + fp16-only out1
// (resid_ln reads fp16 plane; saves ~24MB of HBM traffic).
// ---------------------------------------------------------------------------

#define DD 512
#define NQ  8192
#define NKV 32768
#define EPS 1e-5f

// fp32 scratch planes
#define F_Q   0
#define F_AO  (F_Q  + (size_t)NQ * DD)
#define F_FF  (F_AO + (size_t)NQ * DD)
#define F_WP  (F_FF + (size_t)NQ * DD)          // w_part [NKV][16]
#define F_SW  (F_WP + (size_t)NKV * 16)         // sum-of-w [NQ]
#define F_TOT (F_SW + (size_t)NQ)
__device__ float g_scratch[F_TOT];

// fp16 activation planes
#define B_QH  0
#define B_KH  (B_QH  + (size_t)NQ  * DD)
#define B_VH  (B_KH  + (size_t)NKV * DD)        // downsampled value (NQ rows)
#define B_O1H (B_VH  + (size_t)NQ  * DD)
#define B_HH  (B_O1H + (size_t)NQ  * DD)
#define B_TOT (B_HH  + (size_t)NQ  * DD)
__device__ __half g_act[B_TOT];

// 5 weights x 512x512 fp16, stored [N][K] (transposed)
__device__ __half g_wsplit[5u * 512u * 512u];

// ---------------------------------------------------------------------------
// PTX helpers (base sm_100-legal)
// ---------------------------------------------------------------------------
__device__ __forceinline__ uint32_t smem_u32(const void* p) {
    uint32_t a;
    asm("{ .reg .u64 t; cvta.to.shared.u64 t, %1; cvt.u32.u64 %0, t; }"
        : "=r"(a) : "l"(p));
    return a;
}
__device__ __forceinline__ void ldsm_x4(uint32_t* r, uint32_t addr) {
    asm volatile("ldmatrix.sync.aligned.m8n8.x4.shared.b16 {%0,%1,%2,%3}, [%4];"
                 : "=r"(r[0]), "=r"(r[1]), "=r"(r[2]), "=r"(r[3]) : "r"(addr));
}
__device__ __forceinline__ void mma16816(float* c, const uint32_t* a, const uint32_t* b) {
    asm volatile(
        "mma.sync.aligned.m16n8k16.row.col.f32.f16.f16.f32 "
        "{%0,%1,%2,%3}, {%4,%5,%6,%7}, {%8,%9}, {%0,%1,%2,%3};"
        : "+f"(c[0]), "+f"(c[1]), "+f"(c[2]), "+f"(c[3])
        : "r"(a[0]), "r"(a[1]), "r"(a[2]), "r"(a[3]), "r"(b[0]), "r"(b[1]));
}
__device__ __forceinline__ void cp16(uint32_t saddr, const void* g) {
    asm volatile("cp.async.cg.shared.global [%0], [%1], 16;"
                 :: "r"(saddr), "l"(g) : "memory");
}
__device__ __forceinline__ void cp_commit() {
    asm volatile("cp.async.commit_group;" ::: "memory");
}

// swizzled byte offset of 16B chunk (row, chunk) in a 128x64B plane
__device__ __forceinline__ uint32_t swz_off(uint32_t row, uint32_t chunk) {
    return row * 64u + ((chunk ^ ((row >> 1) & 3u)) << 4);
}

// ---------------------------------------------------------------------------
// Batched weight prep: W[k][n] fp32 -> T[n][k] fp16 (5 weights)
// ---------------------------------------------------------------------------
__global__ void prep_weight5(
    const float* w0, const float* w1, const float* w2, const float* w3, const float* w4,
    __half* base)
{
    const float* Ws[5] = {w0, w1, w2, w3, w4};
    const size_t WSZ = 512u * 512u;
    const float* W = Ws[blockIdx.z];
    __half* Th = base + (size_t)blockIdx.z * WSZ;

    __shared__ float t[32][33];
    const int bx = blockIdx.x * 32, by = blockIdx.y * 32;
    const int tx = threadIdx.x, ty = threadIdx.y; // 32 x 8
#pragma unroll
    for (int i = 0; i < 32; i += 8)
        t[ty + i][tx] = W[(size_t)(by + ty + i) * DD + bx + tx];
    __syncthreads();
#pragma unroll
    for (int i = 0; i < 32; i += 8) {
        size_t o = (size_t)(bx + ty + i) * DD + by + tx;
        Th[o] = __float2half_rn(t[tx][ty + i]);
    }
}

// ---------------------------------------------------------------------------
// fp32 -> fp16 convert (vectorized)
// ---------------------------------------------------------------------------
__global__ void __launch_bounds__(256) f32_to_h(
    const float4* __restrict__ src, uint2* __restrict__ dh)
{
    const int i = blockIdx.x * 256 + threadIdx.x;
    float4 x = src[i];
    __half2 h01, h23;
    h01.x = __float2half_rn(x.x); h01.y = __float2half_rn(x.y);
    h23.x = __float2half_rn(x.z); h23.y = __float2half_rn(x.w);
    uint2 hv;
    hv.x = *(uint32_t*)&h01; hv.y = *(uint32_t*)&h23;
    dh[i] = hv;
}

// ---------------------------------------------------------------------------
// HMMA GEMM: act(A[M,512] @ W[512,512] + bias), fp16 x fp16 -> fp32.
// BM=128, BN=128, BK=32, 256 thr (8 warps 2m x 4n; warp tile 64x32).
// 5-stage cp.async pipeline (16KB stages: Ah|Bh), XOR swizzle,
// 1 barrier/chunk, launch_bounds(256,2) -> 2 CTAs/SM.
// DOTQ: k rows dotted with q rows instead of stored (w partials out).
// OUT_H: write fp16 plane.
// ---------------------------------------------------------------------------
#define BKC 32
#define NCH (DD / BKC)          // 16
#define PLANE 8192              // 128 rows x 64B, swizzled
#define SG_AH 0
#define SG_BH (1 * PLANE)
#define SG_SZ (2 * PLANE)       // 16384
#define STAGES 5
#define GEMM_SMEM (STAGES * SG_SZ) // 81920

template <bool RELU, bool OUT_H, bool DOTQ, bool HASBIAS>
__global__ void __launch_bounds__(256, 2) gemm_h(
    const __half* __restrict__ Ah, const __half* __restrict__ Bh,
    const float* __restrict__ bias, float* __restrict__ C,
    __half* __restrict__ Ch,
    const float* __restrict__ qdot, float* __restrict__ wpart)
{
    extern __shared__ char sm[];
    const uint32_t sb = smem_u32(sm);

    const int tid = threadIdx.x;
    const int lane = tid & 31, wid = tid >> 5;
    const int wm = (wid & 1) * 64;
    const int wn = (wid >> 1) * 32;
    const int bm = blockIdx.y * 128;
    const int bn = blockIdx.x * 128;

    float acc[4][4][4];
#pragma unroll
    for (int i = 0; i < 4; i++)
#pragma unroll
        for (int j = 0; j < 4; j++)
#pragma unroll
            for (int t = 0; t < 4; t++) acc[i][j][t] = 0.f;

    const uint32_t row0 = (uint32_t)(tid >> 2), seg0 = (uint32_t)(tid & 3);
    const uint32_t row1 = row0 + 64;

    auto load_stage = [&](int c, int buf) {
        const uint32_t st = sb + buf * SG_SZ;
        const int kc = c * BKC;
        {
            uint32_t so = swz_off(row0, seg0);
            cp16(st + SG_AH + so, Ah + (size_t)(bm + row0) * DD + kc + seg0 * 8);
            cp16(st + SG_BH + so, Bh + (size_t)(bn + row0) * DD + kc + seg0 * 8);
        }
        {
            uint32_t so = swz_off(row1, seg0);
            cp16(st + SG_AH + so, Ah + (size_t)(bm + row1) * DD + kc + seg0 * 8);
            cp16(st + SG_BH + so, Bh + (size_t)(bn + row1) * DD + kc + seg0 * 8);
        }
        cp_commit();
    };

    const uint32_t a_r = (uint32_t)(wm + (lane & 15));
    const uint32_t a_ch = (uint32_t)(lane >> 4);        // chunk half (0/1)
    const uint32_t b_r = (uint32_t)(wn + ((lane >> 4) << 3) + (lane & 7));
    const uint32_t b_ch = (uint32_t)((lane >> 3) & 1);

    auto compute = [&](int buf) {
        const uint32_t st = sb + buf * SG_SZ;
#pragma unroll
        for (int ks = 0; ks < 2; ks++) {
            uint32_t ah[4][4], bh[2][4];
            const uint32_t kch = (uint32_t)(ks * 2);
#pragma unroll
            for (int i = 0; i < 4; i++) {
                uint32_t off = swz_off(a_r + i * 16, kch + a_ch);
                ldsm_x4(ah[i], st + SG_AH + off);
            }
#pragma unroll
            for (int jp = 0; jp < 2; jp++) {
                uint32_t off = swz_off(b_r + jp * 16, kch + b_ch);
                ldsm_x4(bh[jp], st + SG_BH + off);
            }
#pragma unroll
            for (int i = 0; i < 4; i++)
#pragma unroll
                for (int j = 0; j < 4; j++)
                    mma16816(acc[i][j], ah[i], &bh[j >> 1][(j & 1) * 2]);
        }
    };

    // 5-stage pipeline, one barrier per chunk.
    load_stage(0, 0);
    load_stage(1, 1);
    load_stage(2, 2);
    load_stage(3, 3);

#pragma unroll 1
    for (int c = 0; c < NCH; c++) {
        if (c < NCH - 3)
            asm volatile("cp.async.wait_group 3;" ::: "memory");
        else if (c == NCH - 3)
            asm volatile("cp.async.wait_group 2;" ::: "memory");
        else if (c == NCH - 2)
            asm volatile("cp.async.wait_group 1;" ::: "memory");
        else
            asm volatile("cp.async.wait_group 0;" ::: "memory");
        __syncthreads();
        if (c + 4 < NCH) load_stage(c + 4, (c + 4) % STAGES);
        compute(c % STAGES);
    }

    // ---------------- epilogue ----------------
    const int crow = lane >> 2, ccol = (lane & 3) * 2;

    if (DOTQ) {
        float dotr[4][2];
#pragma unroll
        for (int i = 0; i < 4; i++) { dotr[i][0] = 0.f; dotr[i][1] = 0.f; }
#pragma unroll
        for (int i = 0; i < 4; i++) {
            const int r0 = bm + wm + i * 16 + crow;
            const float* q0p = qdot + (size_t)(r0 >> 2) * DD;
            const float* q1p = qdot + (size_t)((r0 + 8) >> 2) * DD;
#pragma unroll
            for (int j = 0; j < 4; j++) {
                const int col = bn + wn + j * 8 + ccol;
                float bx = 0.f, by = 0.f;
                if (HASBIAS) {
                    float2 bv = *(const float2*)(bias + col);
                    bx = bv.x; by = bv.y;
                }
                float k00 = fmaxf(acc[i][j][0] + bx, 0.f);
                float k01 = fmaxf(acc[i][j][1] + by, 0.f);
                float k10 = fmaxf(acc[i][j][2] + bx, 0.f);
                float k11 = fmaxf(acc[i][j][3] + by, 0.f);
                float2 q0 = *(const float2*)(q0p + col);
                float2 q1 = *(const float2*)(q1p + col);
                dotr[i][0] += k00 * q0.x + k01 * q0.y;
                dotr[i][1] += k10 * q1.x + k11 * q1.y;
            }
        }
#pragma unroll
        for (int i = 0; i < 4; i++)
#pragma unroll
            for (int p = 0; p < 2; p++) {
                float v = dotr[i][p];
                v += __shfl_xor_sync(0xffffffffu, v, 1);
                v += __shfl_xor_sync(0xffffffffu, v, 2);
                if ((lane & 3) == 0) {
                    const int row = bm + wm + i * 16 + crow + p * 8;
                    wpart[(size_t)row * 16 + blockIdx.x * 4 + (wid >> 1)] = v;
                }
            }
        return;
    }

#pragma unroll
    for (int i = 0; i < 4; i++) {
        const int r0 = bm + wm + i * 16 + crow;
#pragma unroll
        for (int j = 0; j < 4; j++) {
            const int col = bn + wn + j * 8 + ccol;
            float bx = 0.f, by = 0.f;
            if (HASBIAS) {
                float2 bv = *(const float2*)(bias + col);
                bx = bv.x; by = bv.y;
            }
            float2 o0, o1;
            o0.x = acc[i][j][0] + bx; o0.y = acc[i][j][1] + by;
            o1.x = acc[i][j][2] + bx; o1.y = acc[i][j][3] + by;
            if (RELU) {
                o0.x = fmaxf(o0.x, 0.f); o0.y = fmaxf(o0.y, 0.f);
                o1.x = fmaxf(o1.x, 0.f); o1.y = fmaxf(o1.y, 0.f);
            }
            if (OUT_H) {
                __half2 h2;
                h2.x = __float2half_rn(o0.x); h2.y = __float2half_rn(o0.y);
                *(__half2*)(Ch + (size_t)r0 * DD + col) = h2;
                h2.x = __float2half_rn(o1.x); h2.y = __float2half_rn(o1.y);
                *(__half2*)(Ch + (size_t)(r0 + 8) * DD + col) = h2;
            } else {
                *(float2*)(C + (size_t)r0 * DD + col) = o0;
                *(float2*)(C + (size_t)(r0 + 8) * DD + col) = o1;
            }
        }
    }
}

// ---------------------------------------------------------------------------
// Downsample: vds[s,:] = sum_f w[4s+f] * value[4s+f,:]; sw[s] = sum_f w.
// ---------------------------------------------------------------------------
__global__ void __launch_bounds__(256) wds_kernel(
    const float* __restrict__ wpart, const float* __restrict__ value,
    __half* __restrict__ vh, float* __restrict__ sw)
{
    const int s = blockIdx.x;
    const int tid = threadIdx.x;
    __shared__ float wp[64];
    __shared__ float wf[4];
    if (tid < 64) wp[tid] = wpart[(size_t)s * 64 + tid];
    __syncthreads();
    if (tid < 4) {
        float a = 0.f;
#pragma unroll
        for (int p = 0; p < 16; p++) a += wp[tid * 16 + p];
        wf[tid] = a;
    }
    __syncthreads();
    const float w0 = wf[0], w1 = wf[1], w2 = wf[2], w3 = wf[3];
    if (tid == 0) sw[s] = w0 + w1 + w2 + w3;

    const float* vr = value + (size_t)s * 4 * DD;
    const size_t o = (size_t)s * DD;
#pragma unroll
    for (int u = 0; u < 2; u++) {
        const int d = tid + u * 256;
        float x = w0 * vr[d] + w1 * vr[DD + d] + w2 * vr[2 * DD + d] + w3 * vr[3 * DD + d];
        vh[o + d] = __float2half_rn(x);
    }
}

// ---------------------------------------------------------------------------
// warp reduction
// ---------------------------------------------------------------------------
__device__ __forceinline__ float warp_sum(float x) {
#pragma unroll
    for (int o = 16; o > 0; o >>= 1) x += __shfl_xor_sync(0xffffffffu, x, o);
    return x;
}

// ---------------------------------------------------------------------------
// LN1: r = q + ao + sw*b_v; out1 = LN(r) -> fp16 plane only
// ---------------------------------------------------------------------------
__global__ void __launch_bounds__(256) attn_ln_kernel(
    const float* __restrict__ q, const float* __restrict__ ao,
    const float* __restrict__ sw, const float* __restrict__ bv,
    const float* __restrict__ gamma, const float* __restrict__ beta,
    __half* __restrict__ outh)
{
    const int row = blockIdx.x;
    const int tid = threadIdx.x;
    const int lane = tid & 31, wid = tid >> 5;
    const size_t off = (size_t)row * DD;
    const float swv = sw[row];

    float r0 = q[off + tid]       + ao[off + tid]       + swv * bv[tid];
    float r1 = q[off + tid + 256] + ao[off + tid + 256] + swv * bv[tid + 256];

    float s = warp_sum(r0 + r1);
    float ss = warp_sum(r0 * r0 + r1 * r1);
    __shared__ float rs[8], rss[8];
    if (lane == 0) { rs[wid] = s; rss[wid] = ss; }
    __syncthreads();
    __shared__ float mv[2];
    if (tid == 0) {
        float S = 0.f, SS = 0.f;
#pragma unroll
        for (int i = 0; i < 8; i++) { S += rs[i]; SS += rss[i]; }
        float mean = S * (1.f / 512.f);
        float var = SS * (1.f / 512.f) - mean * mean;
        mv[0] = mean; mv[1] = rsqrtf(var + EPS);
    }
    __syncthreads();
    const float mean = mv[0], inv = mv[1];
    float y0 = (r0 - mean) * inv * gamma[tid]       + beta[tid];
    float y1 = (r1 - mean) * inv * gamma[tid + 256] + beta[tid + 256];
    outh[off + tid]       = __float2half_rn(y0);
    outh[off + tid + 256] = __float2half_rn(y1);
}

// ---------------------------------------------------------------------------
// Fused residual + LayerNorm2 -> output (out1 read as fp16)
// ---------------------------------------------------------------------------
__global__ void __launch_bounds__(256) resid_ln_kernel(
    const __half* __restrict__ a, const float* __restrict__ f,
    const float* __restrict__ gamma, const float* __restrict__ beta,
    float* __restrict__ out)
{
    const int row = blockIdx.x;
    const int tid = threadIdx.x;
    const int lane = tid & 31, wid = tid >> 5;
    const size_t off = (size_t)row * DD;

    float r0 = __half2float(a[off + tid])       + f[off + tid];
    float r1 = __half2float(a[off + tid + 256]) + f[off + tid + 256];

    float s = warp_sum(r0 + r1);
    float ss = warp_sum(r0 * r0 + r1 * r1);
    __shared__ float rs[8], rss[8];
    if (lane == 0) { rs[wid] = s; rss[wid] = ss; }
    __syncthreads();
    __shared__ float mv[2];
    if (tid == 0) {
        float S = 0.f, SS = 0.f;
#pragma unroll
        for (int i = 0; i < 8; i++) { S += rs[i]; SS += rss[i]; }
        float mean = S * (1.f / 512.f);
        float var = SS * (1.f / 512.f) - mean * mean;
        mv[0] = mean; mv[1] = rsqrtf(var + EPS);
    }
    __syncthreads();
    const float mean = mv[0], inv = mv[1];
    out[off + tid]       = (r0 - mean) * inv * gamma[tid]       + beta[tid];
    out[off + tid + 256] = (r1 - mean) * inv * gamma[tid + 256] + beta[tid + 256];
}

// ---------------------------------------------------------------------------
// Launch
// ---------------------------------------------------------------------------
extern "C" void kernel_launch(void* const* d_in, const int* in_sizes, int n_in,
                              void* d_out, int out_size)
{
    const float* query  = (const float*)d_in[0];
    const float* key    = (const float*)d_in[1];
    const float* value  = (const float*)d_in[2];
    const float* w_q    = (const float*)d_in[3];
    const float* b_q    = (const float*)d_in[4];
    const float* w_k    = (const float*)d_in[5];
    const float* b_k    = (const float*)d_in[6];
    const float* w_v    = (const float*)d_in[7];
    const float* b_v    = (const float*)d_in[8];
    const float* ln1_g  = (const float*)d_in[9];
    const float* ln1_b  = (const float*)d_in[10];
    const float* ln2_g  = (const float*)d_in[11];
    const float* ln2_b  = (const float*)d_in[12];
    const float* ffn_w1 = (const float*)d_in[13];
    const float* ffn_b1 = (const float*)d_in[14];
    const float* ffn_w2 = (const float*)d_in[15];
    const float* ffn_b2 = (const float*)d_in[16];
    float* out = (float*)d_out;

    void* sp = nullptr;
    cudaGetSymbolAddress(&sp, g_scratch);
    float* s = (float*)sp;
    float* g_q    = s + F_Q;
    float* g_ao   = s + F_AO;
    float* g_ffn  = s + F_FF;
    float* g_wp   = s + F_WP;
    float* g_sw   = s + F_SW;

    void* ap = nullptr;
    cudaGetSymbolAddress(&ap, g_act);
    __half* a = (__half*)ap;
    __half* qh  = a + B_QH;
    __half* kh  = a + B_KH;
    __half* vh  = a + B_VH;
    __half* o1h = a + B_O1H;
    __half* hh  = a + B_HH;

    void* wp = nullptr;
    cudaGetSymbolAddress(&wp, g_wsplit);
    __half* w = (__half*)wp;
    const size_t WSZ = 512u * 512u;
    __half* wqh = w + 0 * WSZ;
    __half* wkh = w + 1 * WSZ;
    __half* wvh = w + 2 * WSZ;
    __half* f1h = w + 3 * WSZ;
    __half* f2h = w + 4 * WSZ;

    cudaFuncSetAttribute((const void*)gemm_h<true,  false, false, true >, cudaFuncAttributeMaxDynamicSharedMemorySize, GEMM_SMEM);
    cudaFuncSetAttribute((const void*)gemm_h<true,  false, true,  true >, cudaFuncAttributeMaxDynamicSharedMemorySize, GEMM_SMEM);
    cudaFuncSetAttribute((const void*)gemm_h<false, false, false, false>, cudaFuncAttributeMaxDynamicSharedMemorySize, GEMM_SMEM);
    cudaFuncSetAttribute((const void*)gemm_h<true,  true,  false, true >, cudaFuncAttributeMaxDynamicSharedMemorySize, GEMM_SMEM);
    cudaFuncSetAttribute((const void*)gemm_h<false, false, false, true >, cudaFuncAttributeMaxDynamicSharedMemorySize, GEMM_SMEM);

    const dim3 blk(256);

    prep_weight5<<<dim3(16, 16, 5), dim3(32, 8)>>>(w_q, w_k, w_v, ffn_w1, ffn_w2, w);
    f32_to_h<<<NQ  * DD / 1024, blk>>>((const float4*)query, (uint2*)qh);
    f32_to_h<<<NKV * DD / 1024, blk>>>((const float4*)key,   (uint2*)kh);

    const dim3 grid_q(DD / 128, NQ / 128);   // 4 x 64
    const dim3 grid_kv(DD / 128, NKV / 128); // 4 x 256

    // Q projection
    gemm_h<true, false, false, true><<<grid_q, blk, GEMM_SMEM>>>(
        qh, wqh, b_q, g_q, nullptr, nullptr, nullptr);

    // K projection with fused q.k dot -> w partials
    gemm_h<true, false, true, true><<<grid_kv, blk, GEMM_SMEM>>>(
        kh, wkh, b_k, nullptr, nullptr, g_q, g_wp);

    // downsample raw value by w
    wds_kernel<<<NQ, blk>>>(g_wp, value, vh, g_sw);

    // V projection on downsampled rows
    gemm_h<false, false, false, false><<<grid_q, blk, GEMM_SMEM>>>(
        vh, wvh, nullptr, g_ao, nullptr, nullptr, nullptr);

    // LN1 -> fp16 out1 only
    attn_ln_kernel<<<NQ, blk>>>(g_q, g_ao, g_sw, b_v, ln1_g, ln1_b, o1h);

    // FFN
    gemm_h<true, true, false, true><<<grid_q, blk, GEMM_SMEM>>>(
        o1h, f1h, ffn_b1, nullptr, hh, nullptr, nullptr);
    gemm_h<false, false, false, true><<<grid_q, blk, GEMM_SMEM>>>(
        hh, f2h, ffn_b2, g_ffn, nullptr, nullptr, nullptr);

    resid_ln_kernel<<<NQ, blk>>>(o1h, g_ffn, ln2_g, ln2_b, out);
}

// round 15
// speedup vs baseline: 1.1254x; 1.0135x over previous
#include <cuda_runtime.h>
#include <cuda_bf16.h>
#include <cuda_fp16.h>
#include <cstdint>

// ---------------------------------------------------------------------------
// AttentionSampling: B=4, SQ=2048, SK=8192, D=H=512, F=4, fp32.
// Round 15: R12 GEMM skeleton (single-pass fp16, BK=32, 128x128, XOR swizzle,
// 4-stage, 1 barrier/chunk, 2 CTAs/SM) + fp16-only out1 + stream-overlapped
// prologue (prep || q-convert || key-convert) + fp16 q plane for DOTQ reads.
// ---------------------------------------------------------------------------

#define DD 512
#define NQ  8192
#define NKV 32768
#define EPS 1e-5f

// fp32 scratch planes
#define F_Q   0
#define F_AO  (F_Q  + (size_t)NQ * DD)
#define F_FF  (F_AO + (size_t)NQ * DD)
#define F_WP  (F_FF + (size_t)NQ * DD)          // w_part [NKV][16]
#define F_SW  (F_WP + (size_t)NKV * 16)         // sum-of-w [NQ]
#define F_TOT (F_SW + (size_t)NQ)
__device__ float g_scratch[F_TOT];

// fp16 activation planes
#define B_QH  0
#define B_KH  (B_QH  + (size_t)NQ  * DD)
#define B_VH  (B_KH  + (size_t)NKV * DD)        // downsampled value (NQ rows)
#define B_O1H (B_VH  + (size_t)NQ  * DD)
#define B_HH  (B_O1H + (size_t)NQ  * DD)
#define B_QPH (B_HH  + (size_t)NQ  * DD)        // projected q, fp16 (for DOTQ)
#define B_TOT (B_QPH + (size_t)NQ  * DD)
__device__ __half g_act[B_TOT];

// 5 weights x 512x512 fp16, stored [N][K] (transposed)
__device__ __half g_wsplit[5u * 512u * 512u];

// ---------------------------------------------------------------------------
// PTX helpers (base sm_100-legal)
// ---------------------------------------------------------------------------
__device__ __forceinline__ uint32_t smem_u32(const void* p) {
    uint32_t a;
    asm("{ .reg .u64 t; cvta.to.shared.u64 t, %1; cvt.u32.u64 %0, t; }"
        : "=r"(a) : "l"(p));
    return a;
}
__device__ __forceinline__ void ldsm_x4(uint32_t* r, uint32_t addr) {
    asm volatile("ldmatrix.sync.aligned.m8n8.x4.shared.b16 {%0,%1,%2,%3}, [%4];"
                 : "=r"(r[0]), "=r"(r[1]), "=r"(r[2]), "=r"(r[3]) : "r"(addr));
}
__device__ __forceinline__ void mma16816(float* c, const uint32_t* a, const uint32_t* b) {
    asm volatile(
        "mma.sync.aligned.m16n8k16.row.col.f32.f16.f16.f32 "
        "{%0,%1,%2,%3}, {%4,%5,%6,%7}, {%8,%9}, {%0,%1,%2,%3};"
        : "+f"(c[0]), "+f"(c[1]), "+f"(c[2]), "+f"(c[3])
        : "r"(a[0]), "r"(a[1]), "r"(a[2]), "r"(a[3]), "r"(b[0]), "r"(b[1]));
}
__device__ __forceinline__ void cp16(uint32_t saddr, const void* g) {
    asm volatile("cp.async.cg.shared.global [%0], [%1], 16;"
                 :: "r"(saddr), "l"(g) : "memory");
}
__device__ __forceinline__ void cp_commit() {
    asm volatile("cp.async.commit_group;" ::: "memory");
}

// swizzled byte offset of 16B chunk (row, chunk) in a 128x64B plane
__device__ __forceinline__ uint32_t swz_off(uint32_t row, uint32_t chunk) {
    return row * 64u + ((chunk ^ ((row >> 1) & 3u)) << 4);
}

// ---------------------------------------------------------------------------
// Batched weight prep: W[k][n] fp32 -> T[n][k] fp16 (5 weights)
// ---------------------------------------------------------------------------
__global__ void prep_weight5(
    const float* w0, const float* w1, const float* w2, const float* w3, const float* w4,
    __half* base)
{
    const float* Ws[5] = {w0, w1, w2, w3, w4};
    const size_t WSZ = 512u * 512u;
    const float* W = Ws[blockIdx.z];
    __half* Th = base + (size_t)blockIdx.z * WSZ;

    __shared__ float t[32][33];
    const int bx = blockIdx.x * 32, by = blockIdx.y * 32;
    const int tx = threadIdx.x, ty = threadIdx.y; // 32 x 8
#pragma unroll
    for (int i = 0; i < 32; i += 8)
        t[ty + i][tx] = W[(size_t)(by + ty + i) * DD + bx + tx];
    __syncthreads();
#pragma unroll
    for (int i = 0; i < 32; i += 8) {
        size_t o = (size_t)(bx + ty + i) * DD + by + tx;
        Th[o] = __float2half_rn(t[tx][ty + i]);
    }
}

// ---------------------------------------------------------------------------
// fp32 -> fp16 convert (vectorized)
// ---------------------------------------------------------------------------
__global__ void __launch_bounds__(256) f32_to_h(
    const float4* __restrict__ src, uint2* __restrict__ dh)
{
    const int i = blockIdx.x * 256 + threadIdx.x;
    float4 x = src[i];
    __half2 h01, h23;
    h01.x = __float2half_rn(x.x); h01.y = __float2half_rn(x.y);
    h23.x = __float2half_rn(x.z); h23.y = __float2half_rn(x.w);
    uint2 hv;
    hv.x = *(uint32_t*)&h01; hv.y = *(uint32_t*)&h23;
    dh[i] = hv;
}

// ---------------------------------------------------------------------------
// HMMA GEMM: act(A[M,512] @ W[512,512] + bias), fp16 x fp16 -> fp32.
// BM=128, BN=128, BK=32, 256 thr (8 warps 2m x 4n; warp tile 64x32).
// 4-stage cp.async pipeline (16KB stages: Ah|Bh), XOR swizzle,
// 1 barrier/chunk, launch_bounds(256,2) -> 2 CTAs/SM.
// DOTQ: k rows dotted with fp16 q rows instead of stored (w partials out).
// OUT_H / OUT_F: write fp16 plane / fp32 plane (either or both).
// ---------------------------------------------------------------------------
#define BKC 32
#define NCH (DD / BKC)          // 16
#define PLANE 8192              // 128 rows x 64B, swizzled
#define SG_AH 0
#define SG_BH (1 * PLANE)
#define SG_SZ (2 * PLANE)       // 16384
#define STAGES 4
#define GEMM_SMEM (STAGES * SG_SZ) // 65536

template <bool RELU, bool OUT_H, bool OUT_F, bool DOTQ, bool HASBIAS>
__global__ void __launch_bounds__(256, 2) gemm_h(
    const __half* __restrict__ Ah, const __half* __restrict__ Bh,
    const float* __restrict__ bias, float* __restrict__ C,
    __half* __restrict__ Ch,
    const __half* __restrict__ qdot, float* __restrict__ wpart)
{
    extern __shared__ char sm[];
    const uint32_t sb = smem_u32(sm);

    const int tid = threadIdx.x;
    const int lane = tid & 31, wid = tid >> 5;
    const int wm = (wid & 1) * 64;
    const int wn = (wid >> 1) * 32;
    const int bm = blockIdx.y * 128;
    const int bn = blockIdx.x * 128;

    float acc[4][4][4];
#pragma unroll
    for (int i = 0; i < 4; i++)
#pragma unroll
        for (int j = 0; j < 4; j++)
#pragma unroll
            for (int t = 0; t < 4; t++) acc[i][j][t] = 0.f;

    const uint32_t row0 = (uint32_t)(tid >> 2), seg0 = (uint32_t)(tid & 3);
    const uint32_t row1 = row0 + 64;

    auto load_stage = [&](int c, int buf) {
        const uint32_t st = sb + buf * SG_SZ;
        const int kc = c * BKC;
        {
            uint32_t so = swz_off(row0, seg0);
            cp16(st + SG_AH + so, Ah + (size_t)(bm + row0) * DD + kc + seg0 * 8);
            cp16(st + SG_BH + so, Bh + (size_t)(bn + row0) * DD + kc + seg0 * 8);
        }
        {
            uint32_t so = swz_off(row1, seg0);
            cp16(st + SG_AH + so, Ah + (size_t)(bm + row1) * DD + kc + seg0 * 8);
            cp16(st + SG_BH + so, Bh + (size_t)(bn + row1) * DD + kc + seg0 * 8);
        }
        cp_commit();
    };

    const uint32_t a_r = (uint32_t)(wm + (lane & 15));
    const uint32_t a_ch = (uint32_t)(lane >> 4);        // chunk half (0/1)
    const uint32_t b_r = (uint32_t)(wn + ((lane >> 4) << 3) + (lane & 7));
    const uint32_t b_ch = (uint32_t)((lane >> 3) & 1);

    auto compute = [&](int buf) {
        const uint32_t st = sb + buf * SG_SZ;
#pragma unroll
        for (int ks = 0; ks < 2; ks++) {
            uint32_t ah[4][4], bh[2][4];
            const uint32_t kch = (uint32_t)(ks * 2);
#pragma unroll
            for (int i = 0; i < 4; i++) {
                uint32_t off = swz_off(a_r + i * 16, kch + a_ch);
                ldsm_x4(ah[i], st + SG_AH + off);
            }
#pragma unroll
            for (int jp = 0; jp < 2; jp++) {
                uint32_t off = swz_off(b_r + jp * 16, kch + b_ch);
                ldsm_x4(bh[jp], st + SG_BH + off);
            }
#pragma unroll
            for (int i = 0; i < 4; i++)
#pragma unroll
                for (int j = 0; j < 4; j++)
                    mma16816(acc[i][j], ah[i], &bh[j >> 1][(j & 1) * 2]);
        }
    };

    // 4-stage pipeline, one barrier per chunk.
    load_stage(0, 0);
    load_stage(1, 1);
    load_stage(2, 2);

#pragma unroll 1
    for (int c = 0; c < NCH; c++) {
        if (c < NCH - 2)
            asm volatile("cp.async.wait_group 2;" ::: "memory");
        else if (c == NCH - 2)
            asm volatile("cp.async.wait_group 1;" ::: "memory");
        else
            asm volatile("cp.async.wait_group 0;" ::: "memory");
        __syncthreads();
        if (c + 3 < NCH) load_stage(c + 3, (c + 3) & 3);
        compute(c & 3);
    }

    // ---------------- epilogue ----------------
    const int crow = lane >> 2, ccol = (lane & 3) * 2;

    if (DOTQ) {
        float dotr[4][2];
#pragma unroll
        for (int i = 0; i < 4; i++) { dotr[i][0] = 0.f; dotr[i][1] = 0.f; }
#pragma unroll
        for (int i = 0; i < 4; i++) {
            const int r0 = bm + wm + i * 16 + crow;
            const __half* q0p = qdot + (size_t)(r0 >> 2) * DD;
            const __half* q1p = qdot + (size_t)((r0 + 8) >> 2) * DD;
#pragma unroll
            for (int j = 0; j < 4; j++) {
                const int col = bn + wn + j * 8 + ccol;
                float bx = 0.f, by = 0.f;
                if (HASBIAS) {
                    float2 bv = *(const float2*)(bias + col);
                    bx = bv.x; by = bv.y;
                }
                float k00 = fmaxf(acc[i][j][0] + bx, 0.f);
                float k01 = fmaxf(acc[i][j][1] + by, 0.f);
                float k10 = fmaxf(acc[i][j][2] + bx, 0.f);
                float k11 = fmaxf(acc[i][j][3] + by, 0.f);
                float2 q0 = __half22float2(*(const __half2*)(q0p + col));
                float2 q1 = __half22float2(*(const __half2*)(q1p + col));
                dotr[i][0] += k00 * q0.x + k01 * q0.y;
                dotr[i][1] += k10 * q1.x + k11 * q1.y;
            }
        }
#pragma unroll
        for (int i = 0; i < 4; i++)
#pragma unroll
            for (int p = 0; p < 2; p++) {
                float v = dotr[i][p];
                v += __shfl_xor_sync(0xffffffffu, v, 1);
                v += __shfl_xor_sync(0xffffffffu, v, 2);
                if ((lane & 3) == 0) {
                    const int row = bm + wm + i * 16 + crow + p * 8;
                    wpart[(size_t)row * 16 + blockIdx.x * 4 + (wid >> 1)] = v;
                }
            }
        return;
    }

#pragma unroll
    for (int i = 0; i < 4; i++) {
        const int r0 = bm + wm + i * 16 + crow;
#pragma unroll
        for (int j = 0; j < 4; j++) {
            const int col = bn + wn + j * 8 + ccol;
            float bx = 0.f, by = 0.f;
            if (HASBIAS) {
                float2 bv = *(const float2*)(bias + col);
                bx = bv.x; by = bv.y;
            }
            float2 o0, o1;
            o0.x = acc[i][j][0] + bx; o0.y = acc[i][j][1] + by;
            o1.x = acc[i][j][2] + bx; o1.y = acc[i][j][3] + by;
            if (RELU) {
                o0.x = fmaxf(o0.x, 0.f); o0.y = fmaxf(o0.y, 0.f);
                o1.x = fmaxf(o1.x, 0.f); o1.y = fmaxf(o1.y, 0.f);
            }
            if (OUT_F) {
                *(float2*)(C + (size_t)r0 * DD + col) = o0;
                *(float2*)(C + (size_t)(r0 + 8) * DD + col) = o1;
            }
            if (OUT_H) {
                __half2 h2;
                h2.x = __float2half_rn(o0.x); h2.y = __float2half_rn(o0.y);
                *(__half2*)(Ch + (size_t)r0 * DD + col) = h2;
                h2.x = __float2half_rn(o1.x); h2.y = __float2half_rn(o1.y);
                *(__half2*)(Ch + (size_t)(r0 + 8) * DD + col) = h2;
            }
        }
    }
}

// ---------------------------------------------------------------------------
// Downsample: vds[s,:] = sum_f w[4s+f] * value[4s+f,:]; sw[s] = sum_f w.
// ---------------------------------------------------------------------------
__global__ void __launch_bounds__(256) wds_kernel(
    const float* __restrict__ wpart, const float* __restrict__ value,
    __half* __restrict__ vh, float* __restrict__ sw)
{
    const int s = blockIdx.x;
    const int tid = threadIdx.x;
    __shared__ float wp[64];
    __shared__ float wf[4];
    if (tid < 64) wp[tid] = wpart[(size_t)s * 64 + tid];
    __syncthreads();
    if (tid < 4) {
        float a = 0.f;
#pragma unroll
        for (int p = 0; p < 16; p++) a += wp[tid * 16 + p];
        wf[tid] = a;
    }
    __syncthreads();
    const float w0 = wf[0], w1 = wf[1], w2 = wf[2], w3 = wf[3];
    if (tid == 0) sw[s] = w0 + w1 + w2 + w3;

    const float* vr = value + (size_t)s * 4 * DD;
    const size_t o = (size_t)s * DD;
#pragma unroll
    for (int u = 0; u < 2; u++) {
        const int d = tid + u * 256;
        float x = w0 * vr[d] + w1 * vr[DD + d] + w2 * vr[2 * DD + d] + w3 * vr[3 * DD + d];
        vh[o + d] = __float2half_rn(x);
    }
}

// ---------------------------------------------------------------------------
// warp reduction
// ---------------------------------------------------------------------------
__device__ __forceinline__ float warp_sum(float x) {
#pragma unroll
    for (int o = 16; o > 0; o >>= 1) x += __shfl_xor_sync(0xffffffffu, x, o);
    return x;
}

// ---------------------------------------------------------------------------
// LN1: r = q + ao + sw*b_v; out1 = LN(r) -> fp16 plane only
// ---------------------------------------------------------------------------
__global__ void __launch_bounds__(256) attn_ln_kernel(
    const float* __restrict__ q, const float* __restrict__ ao,
    const float* __restrict__ sw, const float* __restrict__ bv,
    const float* __restrict__ gamma, const float* __restrict__ beta,
    __half* __restrict__ outh)
{
    const int row = blockIdx.x;
    const int tid = threadIdx.x;
    const int lane = tid & 31, wid = tid >> 5;
    const size_t off = (size_t)row * DD;
    const float swv = sw[row];

    float r0 = q[off + tid]       + ao[off + tid]       + swv * bv[tid];
    float r1 = q[off + tid + 256] + ao[off + tid + 256] + swv * bv[tid + 256];

    float s = warp_sum(r0 + r1);
    float ss = warp_sum(r0 * r0 + r1 * r1);
    __shared__ float rs[8], rss[8];
    if (lane == 0) { rs[wid] = s; rss[wid] = ss; }
    __syncthreads();
    __shared__ float mv[2];
    if (tid == 0) {
        float S = 0.f, SS = 0.f;
#pragma unroll
        for (int i = 0; i < 8; i++) { S += rs[i]; SS += rss[i]; }
        float mean = S * (1.f / 512.f);
        float var = SS * (1.f / 512.f) - mean * mean;
        mv[0] = mean; mv[1] = rsqrtf(var + EPS);
    }
    __syncthreads();
    const float mean = mv[0], inv = mv[1];
    float y0 = (r0 - mean) * inv * gamma[tid]       + beta[tid];
    float y1 = (r1 - mean) * inv * gamma[tid + 256] + beta[tid + 256];
    outh[off + tid]       = __float2half_rn(y0);
    outh[off + tid + 256] = __float2half_rn(y1);
}

// ---------------------------------------------------------------------------
// Fused residual + LayerNorm2 -> output (out1 read as fp16)
// ---------------------------------------------------------------------------
__global__ void __launch_bounds__(256) resid_ln_kernel(
    const __half* __restrict__ a, const float* __restrict__ f,
    const float* __restrict__ gamma, const float* __restrict__ beta,
    float* __restrict__ out)
{
    const int row = blockIdx.x;
    const int tid = threadIdx.x;
    const int lane = tid & 31, wid = tid >> 5;
    const size_t off = (size_t)row * DD;

    float r0 = __half2float(a[off + tid])       + f[off + tid];
    float r1 = __half2float(a[off + tid + 256]) + f[off + tid + 256];

    float s = warp_sum(r0 + r1);
    float ss = warp_sum(r0 * r0 + r1 * r1);
    __shared__ float rs[8], rss[8];
    if (lane == 0) { rs[wid] = s; rss[wid] = ss; }
    __syncthreads();
    __shared__ float mv[2];
    if (tid == 0) {
        float S = 0.f, SS = 0.f;
#pragma unroll
        for (int i = 0; i < 8; i++) { S += rs[i]; SS += rss[i]; }
        float mean = S * (1.f / 512.f);
        float var = SS * (1.f / 512.f) - mean * mean;
        mv[0] = mean; mv[1] = rsqrtf(var + EPS);
    }
    __syncthreads();
    const float mean = mv[0], inv = mv[1];
    out[off + tid]       = (r0 - mean) * inv * gamma[tid]       + beta[tid];
    out[off + tid + 256] = (r1 - mean) * inv * gamma[tid + 256] + beta[tid + 256];
}

// ---------------------------------------------------------------------------
// Launch (prologue forked across streams; capture-safe fork/join via events)
// ---------------------------------------------------------------------------
extern "C" void kernel_launch(void* const* d_in, const int* in_sizes, int n_in,
                              void* d_out, int out_size)
{
    const float* query  = (const float*)d_in[0];
    const float* key    = (const float*)d_in[1];
    const float* value  = (const float*)d_in[2];
    const float* w_q    = (const float*)d_in[3];
    const float* b_q    = (const float*)d_in[4];
    const float* w_k    = (const float*)d_in[5];
    const float* b_k    = (const float*)d_in[6];
    const float* w_v    = (const float*)d_in[7];
    const float* b_v    = (const float*)d_in[8];
    const float* ln1_g  = (const float*)d_in[9];
    const float* ln1_b  = (const float*)d_in[10];
    const float* ln2_g  = (const float*)d_in[11];
    const float* ln2_b  = (const float*)d_in[12];
    const float* ffn_w1 = (const float*)d_in[13];
    const float* ffn_b1 = (const float*)d_in[14];
    const float* ffn_w2 = (const float*)d_in[15];
    const float* ffn_b2 = (const float*)d_in[16];
    float* out = (float*)d_out;

    void* sp = nullptr;
    cudaGetSymbolAddress(&sp, g_scratch);
    float* s = (float*)sp;
    float* g_q    = s + F_Q;
    float* g_ao   = s + F_AO;
    float* g_ffn  = s + F_FF;
    float* g_wp   = s + F_WP;
    float* g_sw   = s + F_SW;

    void* ap = nullptr;
    cudaGetSymbolAddress(&ap, g_act);
    __half* a = (__half*)ap;
    __half* qh  = a + B_QH;
    __half* kh  = a + B_KH;
    __half* vh  = a + B_VH;
    __half* o1h = a + B_O1H;
    __half* hh  = a + B_HH;
    __half* qph = a + B_QPH;

    void* wp = nullptr;
    cudaGetSymbolAddress(&wp, g_wsplit);
    __half* w = (__half*)wp;
    const size_t WSZ = 512u * 512u;
    __half* wqh = w + 0 * WSZ;
    __half* wkh = w + 1 * WSZ;
    __half* wvh = w + 2 * WSZ;
    __half* f1h = w + 3 * WSZ;
    __half* f2h = w + 4 * WSZ;

    cudaFuncSetAttribute((const void*)gemm_h<true,  true,  true,  false, true >, cudaFuncAttributeMaxDynamicSharedMemorySize, GEMM_SMEM);
    cudaFuncSetAttribute((const void*)gemm_h<true,  false, false, true,  true >, cudaFuncAttributeMaxDynamicSharedMemorySize, GEMM_SMEM);
    cudaFuncSetAttribute((const void*)gemm_h<false, false, true,  false, false>, cudaFuncAttributeMaxDynamicSharedMemorySize, GEMM_SMEM);
    cudaFuncSetAttribute((const void*)gemm_h<true,  true,  false, false, true >, cudaFuncAttributeMaxDynamicSharedMemorySize, GEMM_SMEM);
    cudaFuncSetAttribute((const void*)gemm_h<false, false, true,  false, true >, cudaFuncAttributeMaxDynamicSharedMemorySize, GEMM_SMEM);

    // side streams + events (created once, before any capture; reused since)
    static cudaStream_t s1 = nullptr, s2 = nullptr;
    static cudaEvent_t e0 = nullptr, e1 = nullptr, e2 = nullptr;
    if (s1 == nullptr) {
        cudaStreamCreateWithFlags(&s1, cudaStreamNonBlocking);
        cudaStreamCreateWithFlags(&s2, cudaStreamNonBlocking);
        cudaEventCreateWithFlags(&e0, cudaEventDisableTiming);
        cudaEventCreateWithFlags(&e1, cudaEventDisableTiming);
        cudaEventCreateWithFlags(&e2, cudaEventDisableTiming);
    }

    const dim3 blk(256);
    const dim3 grid_q(DD / 128, NQ / 128);   // 4 x 64
    const dim3 grid_kv(DD / 128, NKV / 128); // 4 x 256

    // fork: prep (main) || q convert (s1) || key convert (s2)
    cudaEventRecord(e0, 0);
    cudaStreamWaitEvent(s1, e0, 0);
    cudaStreamWaitEvent(s2, e0, 0);

    prep_weight5<<<dim3(16, 16, 5), dim3(32, 8)>>>(w_q, w_k, w_v, ffn_w1, ffn_w2, w);
    f32_to_h<<<NQ  * DD / 1024, blk, 0, s1>>>((const float4*)query, (uint2*)qh);
    f32_to_h<<<NKV * DD / 1024, blk, 0, s2>>>((const float4*)key,   (uint2*)kh);

    cudaEventRecord(e1, s1);
    cudaEventRecord(e2, s2);

    // Q projection (needs prep + qh): fp32 q (LN1) + fp16 q (DOTQ)
    cudaStreamWaitEvent(0, e1, 0);
    gemm_h<true, true, true, false, true><<<grid_q, blk, GEMM_SMEM>>>(
        qh, wqh, b_q, g_q, qph, nullptr, nullptr);

    // K projection with fused q.k dot (needs kh + qph)
    cudaStreamWaitEvent(0, e2, 0);
    gemm_h<true, false, false, true, true><<<grid_kv, blk, GEMM_SMEM>>>(
        kh, wkh, b_k, nullptr, nullptr, qph, g_wp);

    // downsample raw value by w
    wds_kernel<<<NQ, blk>>>(g_wp, value, vh, g_sw);

    // V projection on downsampled rows
    gemm_h<false, false, true, false, false><<<grid_q, blk, GEMM_SMEM>>>(
        vh, wvh, nullptr, g_ao, nullptr, nullptr, nullptr);

    // LN1 -> fp16 out1 only
    attn_ln_kernel<<<NQ, blk>>>(g_q, g_ao, g_sw, b_v, ln1_g, ln1_b, o1h);

    // FFN
    gemm_h<true, true, false, false, true><<<grid_q, blk, GEMM_SMEM>>>(
        o1h, f1h, ffn_b1, nullptr, hh, nullptr, nullptr);
    gemm_h<false, false, true, false, true><<<grid_q, blk, GEMM_SMEM>>>(
        hh, f2h, ffn_b2, g_ffn, nullptr, nullptr, nullptr);

    resid_ln_kernel<<<NQ, blk>>>(o1h, g_ffn, ln2_g, ln2_b, out);
}

// round 16
// speedup vs baseline: 1.1459x; 1.0182x over previous
#include <cuda_runtime.h>
#include <cuda_bf16.h>
#include <cuda_fp16.h>
#include <cstdint>

// ---------------------------------------------------------------------------
// AttentionSampling: B=4, SQ=2048, SK=8192, D=H=512, F=4, fp32.
// Round 16: all activations fp16 single-plane end-to-end (q fp32 plane
// dropped; attn_ln reads fp16 q). R12 GEMM skeleton: single-pass fp16,
// BK=32, 128x128, XOR swizzle, 4-stage, 1 barrier/chunk, 2 CTAs/SM.
// Stream-overlapped prologue kept.
// ---------------------------------------------------------------------------

#define DD 512
#define NQ  8192
#define NKV 32768
#define EPS 1e-5f

// fp32 scratch planes
#define F_AO  0
#define F_FF  (F_AO + (size_t)NQ * DD)
#define F_WP  (F_FF + (size_t)NQ * DD)          // w_part [NKV][16]
#define F_SW  (F_WP + (size_t)NKV * 16)         // sum-of-w [NQ]
#define F_TOT (F_SW + (size_t)NQ)
__device__ float g_scratch[F_TOT];

// fp16 activation planes
#define B_QH  0
#define B_KH  (B_QH  + (size_t)NQ  * DD)
#define B_VH  (B_KH  + (size_t)NKV * DD)        // downsampled value (NQ rows)
#define B_O1H (B_VH  + (size_t)NQ  * DD)
#define B_HH  (B_O1H + (size_t)NQ  * DD)
#define B_QPH (B_HH  + (size_t)NQ  * DD)        // projected q, fp16
#define B_TOT (B_QPH + (size_t)NQ  * DD)
__device__ __half g_act[B_TOT];

// 5 weights x 512x512 fp16, stored [N][K] (transposed)
__device__ __half g_wsplit[5u * 512u * 512u];

// ---------------------------------------------------------------------------
// PTX helpers (base sm_100-legal)
// ---------------------------------------------------------------------------
__device__ __forceinline__ uint32_t smem_u32(const void* p) {
    uint32_t a;
    asm("{ .reg .u64 t; cvta.to.shared.u64 t, %1; cvt.u32.u64 %0, t; }"
        : "=r"(a) : "l"(p));
    return a;
}
__device__ __forceinline__ void ldsm_x4(uint32_t* r, uint32_t addr) {
    asm volatile("ldmatrix.sync.aligned.m8n8.x4.shared.b16 {%0,%1,%2,%3}, [%4];"
                 : "=r"(r[0]), "=r"(r[1]), "=r"(r[2]), "=r"(r[3]) : "r"(addr));
}
__device__ __forceinline__ void mma16816(float* c, const uint32_t* a, const uint32_t* b) {
    asm volatile(
        "mma.sync.aligned.m16n8k16.row.col.f32.f16.f16.f32 "
        "{%0,%1,%2,%3}, {%4,%5,%6,%7}, {%8,%9}, {%0,%1,%2,%3};"
        : "+f"(c[0]), "+f"(c[1]), "+f"(c[2]), "+f"(c[3])
        : "r"(a[0]), "r"(a[1]), "r"(a[2]), "r"(a[3]), "r"(b[0]), "r"(b[1]));
}
__device__ __forceinline__ void cp16(uint32_t saddr, const void* g) {
    asm volatile("cp.async.cg.shared.global [%0], [%1], 16;"
                 :: "r"(saddr), "l"(g) : "memory");
}
__device__ __forceinline__ void cp_commit() {
    asm volatile("cp.async.commit_group;" ::: "memory");
}

// swizzled byte offset of 16B chunk (row, chunk) in a 128x64B plane
__device__ __forceinline__ uint32_t swz_off(uint32_t row, uint32_t chunk) {
    return row * 64u + ((chunk ^ ((row >> 1) & 3u)) << 4);
}

// ---------------------------------------------------------------------------
// Batched weight prep: W[k][n] fp32 -> T[n][k] fp16 (5 weights)
// ---------------------------------------------------------------------------
__global__ void prep_weight5(
    const float* w0, const float* w1, const float* w2, const float* w3, const float* w4,
    __half* base)
{
    const float* Ws[5] = {w0, w1, w2, w3, w4};
    const size_t WSZ = 512u * 512u;
    const float* W = Ws[blockIdx.z];
    __half* Th = base + (size_t)blockIdx.z * WSZ;

    __shared__ float t[32][33];
    const int bx = blockIdx.x * 32, by = blockIdx.y * 32;
    const int tx = threadIdx.x, ty = threadIdx.y; // 32 x 8
#pragma unroll
    for (int i = 0; i < 32; i += 8)
        t[ty + i][tx] = W[(size_t)(by + ty + i) * DD + bx + tx];
    __syncthreads();
#pragma unroll
    for (int i = 0; i < 32; i += 8) {
        size_t o = (size_t)(bx + ty + i) * DD + by + tx;
        Th[o] = __float2half_rn(t[tx][ty + i]);
    }
}

// ---------------------------------------------------------------------------
// fp32 -> fp16 convert (vectorized)
// ---------------------------------------------------------------------------
__global__ void __launch_bounds__(256) f32_to_h(
    const float4* __restrict__ src, uint2* __restrict__ dh)
{
    const int i = blockIdx.x * 256 + threadIdx.x;
    float4 x = src[i];
    __half2 h01, h23;
    h01.x = __float2half_rn(x.x); h01.y = __float2half_rn(x.y);
    h23.x = __float2half_rn(x.z); h23.y = __float2half_rn(x.w);
    uint2 hv;
    hv.x = *(uint32_t*)&h01; hv.y = *(uint32_t*)&h23;
    dh[i] = hv;
}

// ---------------------------------------------------------------------------
// HMMA GEMM: act(A[M,512] @ W[512,512] + bias), fp16 x fp16 -> fp32.
// BM=128, BN=128, BK=32, 256 thr (8 warps 2m x 4n; warp tile 64x32).
// 4-stage cp.async pipeline (16KB stages: Ah|Bh), XOR swizzle,
// 1 barrier/chunk, launch_bounds(256,2) -> 2 CTAs/SM.
// DOTQ: k rows dotted with fp16 q rows instead of stored (w partials out).
// OUT_H / OUT_F: write fp16 / fp32 plane.
// ---------------------------------------------------------------------------
#define BKC 32
#define NCH (DD / BKC)          // 16
#define PLANE 8192              // 128 rows x 64B, swizzled
#define SG_AH 0
#define SG_BH (1 * PLANE)
#define SG_SZ (2 * PLANE)       // 16384
#define STAGES 4
#define GEMM_SMEM (STAGES * SG_SZ) // 65536

template <bool RELU, bool OUT_H, bool OUT_F, bool DOTQ, bool HASBIAS>
__global__ void __launch_bounds__(256, 2) gemm_h(
    const __half* __restrict__ Ah, const __half* __restrict__ Bh,
    const float* __restrict__ bias, float* __restrict__ C,
    __half* __restrict__ Ch,
    const __half* __restrict__ qdot, float* __restrict__ wpart)
{
    extern __shared__ char sm[];
    const uint32_t sb = smem_u32(sm);

    const int tid = threadIdx.x;
    const int lane = tid & 31, wid = tid >> 5;
    const int wm = (wid & 1) * 64;
    const int wn = (wid >> 1) * 32;
    const int bm = blockIdx.y * 128;
    const int bn = blockIdx.x * 128;

    float acc[4][4][4];
#pragma unroll
    for (int i = 0; i < 4; i++)
#pragma unroll
        for (int j = 0; j < 4; j++)
#pragma unroll
            for (int t = 0; t < 4; t++) acc[i][j][t] = 0.f;

    const uint32_t row0 = (uint32_t)(tid >> 2), seg0 = (uint32_t)(tid & 3);
    const uint32_t row1 = row0 + 64;

    auto load_stage = [&](int c, int buf) {
        const uint32_t st = sb + buf * SG_SZ;
        const int kc = c * BKC;
        {
            uint32_t so = swz_off(row0, seg0);
            cp16(st + SG_AH + so, Ah + (size_t)(bm + row0) * DD + kc + seg0 * 8);
            cp16(st + SG_BH + so, Bh + (size_t)(bn + row0) * DD + kc + seg0 * 8);
        }
        {
            uint32_t so = swz_off(row1, seg0);
            cp16(st + SG_AH + so, Ah + (size_t)(bm + row1) * DD + kc + seg0 * 8);
            cp16(st + SG_BH + so, Bh + (size_t)(bn + row1) * DD + kc + seg0 * 8);
        }
        cp_commit();
    };

    const uint32_t a_r = (uint32_t)(wm + (lane & 15));
    const uint32_t a_ch = (uint32_t)(lane >> 4);        // chunk half (0/1)
    const uint32_t b_r = (uint32_t)(wn + ((lane >> 4) << 3) + (lane & 7));
    const uint32_t b_ch = (uint32_t)((lane >> 3) & 1);

    auto compute = [&](int buf) {
        const uint32_t st = sb + buf * SG_SZ;
#pragma unroll
        for (int ks = 0; ks < 2; ks++) {
            uint32_t ah[4][4], bh[2][4];
            const uint32_t kch = (uint32_t)(ks * 2);
#pragma unroll
            for (int i = 0; i < 4; i++) {
                uint32_t off = swz_off(a_r + i * 16, kch + a_ch);
                ldsm_x4(ah[i], st + SG_AH + off);
            }
#pragma unroll
            for (int jp = 0; jp < 2; jp++) {
                uint32_t off = swz_off(b_r + jp * 16, kch + b_ch);
                ldsm_x4(bh[jp], st + SG_BH + off);
            }
#pragma unroll
            for (int i = 0; i < 4; i++)
#pragma unroll
                for (int j = 0; j < 4; j++)
                    mma16816(acc[i][j], ah[i], &bh[j >> 1][(j & 1) * 2]);
        }
    };

    // 4-stage pipeline, one barrier per chunk.
    load_stage(0, 0);
    load_stage(1, 1);
    load_stage(2, 2);

#pragma unroll 1
    for (int c = 0; c < NCH; c++) {
        if (c < NCH - 2)
            asm volatile("cp.async.wait_group 2;" ::: "memory");
        else if (c == NCH - 2)
            asm volatile("cp.async.wait_group 1;" ::: "memory");
        else
            asm volatile("cp.async.wait_group 0;" ::: "memory");
        __syncthreads();
        if (c + 3 < NCH) load_stage(c + 3, (c + 3) & 3);
        compute(c & 3);
    }

    // ---------------- epilogue ----------------
    const int crow = lane >> 2, ccol = (lane & 3) * 2;

    if (DOTQ) {
        float dotr[4][2];
#pragma unroll
        for (int i = 0; i < 4; i++) { dotr[i][0] = 0.f; dotr[i][1] = 0.f; }
#pragma unroll
        for (int i = 0; i < 4; i++) {
            const int r0 = bm + wm + i * 16 + crow;
            const __half* q0p = qdot + (size_t)(r0 >> 2) * DD;
            const __half* q1p = qdot + (size_t)((r0 + 8) >> 2) * DD;
#pragma unroll
            for (int j = 0; j < 4; j++) {
                const int col = bn + wn + j * 8 + ccol;
                float bx = 0.f, by = 0.f;
                if (HASBIAS) {
                    float2 bv = *(const float2*)(bias + col);
                    bx = bv.x; by = bv.y;
                }
                float k00 = fmaxf(acc[i][j][0] + bx, 0.f);
                float k01 = fmaxf(acc[i][j][1] + by, 0.f);
                float k10 = fmaxf(acc[i][j][2] + bx, 0.f);
                float k11 = fmaxf(acc[i][j][3] + by, 0.f);
                float2 q0 = __half22float2(*(const __half2*)(q0p + col));
                float2 q1 = __half22float2(*(const __half2*)(q1p + col));
                dotr[i][0] += k00 * q0.x + k01 * q0.y;
                dotr[i][1] += k10 * q1.x + k11 * q1.y;
            }
        }
#pragma unroll
        for (int i = 0; i < 4; i++)
#pragma unroll
            for (int p = 0; p < 2; p++) {
                float v = dotr[i][p];
                v += __shfl_xor_sync(0xffffffffu, v, 1);
                v += __shfl_xor_sync(0xffffffffu, v, 2);
                if ((lane & 3) == 0) {
                    const int row = bm + wm + i * 16 + crow + p * 8;
                    wpart[(size_t)row * 16 + blockIdx.x * 4 + (wid >> 1)] = v;
                }
            }
        return;
    }

#pragma unroll
    for (int i = 0; i < 4; i++) {
        const int r0 = bm + wm + i * 16 + crow;
#pragma unroll
        for (int j = 0; j < 4; j++) {
            const int col = bn + wn + j * 8 + ccol;
            float bx = 0.f, by = 0.f;
            if (HASBIAS) {
                float2 bv = *(const float2*)(bias + col);
                bx = bv.x; by = bv.y;
            }
            float2 o0, o1;
            o0.x = acc[i][j][0] + bx; o0.y = acc[i][j][1] + by;
            o1.x = acc[i][j][2] + bx; o1.y = acc[i][j][3] + by;
            if (RELU) {
                o0.x = fmaxf(o0.x, 0.f); o0.y = fmaxf(o0.y, 0.f);
                o1.x = fmaxf(o1.x, 0.f); o1.y = fmaxf(o1.y, 0.f);
            }
            if (OUT_F) {
                *(float2*)(C + (size_t)r0 * DD + col) = o0;
                *(float2*)(C + (size_t)(r0 + 8) * DD + col) = o1;
            }
            if (OUT_H) {
                __half2 h2;
                h2.x = __float2half_rn(o0.x); h2.y = __float2half_rn(o0.y);
                *(__half2*)(Ch + (size_t)r0 * DD + col) = h2;
                h2.x = __float2half_rn(o1.x); h2.y = __float2half_rn(o1.y);
                *(__half2*)(Ch + (size_t)(r0 + 8) * DD + col) = h2;
            }
        }
    }
}

// ---------------------------------------------------------------------------
// Downsample: vds[s,:] = sum_f w[4s+f] * value[4s+f,:]; sw[s] = sum_f w.
// ---------------------------------------------------------------------------
__global__ void __launch_bounds__(256) wds_kernel(
    const float* __restrict__ wpart, const float* __restrict__ value,
    __half* __restrict__ vh, float* __restrict__ sw)
{
    const int s = blockIdx.x;
    const int tid = threadIdx.x;
    __shared__ float wp[64];
    __shared__ float wf[4];
    if (tid < 64) wp[tid] = wpart[(size_t)s * 64 + tid];
    __syncthreads();
    if (tid < 4) {
        float a = 0.f;
#pragma unroll
        for (int p = 0; p < 16; p++) a += wp[tid * 16 + p];
        wf[tid] = a;
    }
    __syncthreads();
    const float w0 = wf[0], w1 = wf[1], w2 = wf[2], w3 = wf[3];
    if (tid == 0) sw[s] = w0 + w1 + w2 + w3;

    const float* vr = value + (size_t)s * 4 * DD;
    const size_t o = (size_t)s * DD;
#pragma unroll
    for (int u = 0; u < 2; u++) {
        const int d = tid + u * 256;
        float x = w0 * vr[d] + w1 * vr[DD + d] + w2 * vr[2 * DD + d] + w3 * vr[3 * DD + d];
        vh[o + d] = __float2half_rn(x);
    }
}

// ---------------------------------------------------------------------------
// warp reduction
// ---------------------------------------------------------------------------
__device__ __forceinline__ float warp_sum(float x) {
#pragma unroll
    for (int o = 16; o > 0; o >>= 1) x += __shfl_xor_sync(0xffffffffu, x, o);
    return x;
}

// ---------------------------------------------------------------------------
// LN1: r = q(fp16) + ao + sw*b_v; out1 = LN(r) -> fp16 plane
// ---------------------------------------------------------------------------
__global__ void __launch_bounds__(256) attn_ln_kernel(
    const __half* __restrict__ q, const float* __restrict__ ao,
    const float* __restrict__ sw, const float* __restrict__ bv,
    const float* __restrict__ gamma, const float* __restrict__ beta,
    __half* __restrict__ outh)
{
    const int row = blockIdx.x;
    const int tid = threadIdx.x;
    const int lane = tid & 31, wid = tid >> 5;
    const size_t off = (size_t)row * DD;
    const float swv = sw[row];

    float r0 = __half2float(q[off + tid])       + ao[off + tid]       + swv * bv[tid];
    float r1 = __half2float(q[off + tid + 256]) + ao[off + tid + 256] + swv * bv[tid + 256];

    float s = warp_sum(r0 + r1);
    float ss = warp_sum(r0 * r0 + r1 * r1);
    __shared__ float rs[8], rss[8];
    if (lane == 0) { rs[wid] = s; rss[wid] = ss; }
    __syncthreads();
    __shared__ float mv[2];
    if (tid == 0) {
        float S = 0.f, SS = 0.f;
#pragma unroll
        for (int i = 0; i < 8; i++) { S += rs[i]; SS += rss[i]; }
        float mean = S * (1.f / 512.f);
        float var = SS * (1.f / 512.f) - mean * mean;
        mv[0] = mean; mv[1] = rsqrtf(var + EPS);
    }
    __syncthreads();
    const float mean = mv[0], inv = mv[1];
    float y0 = (r0 - mean) * inv * gamma[tid]       + beta[tid];
    float y1 = (r1 - mean) * inv * gamma[tid + 256] + beta[tid + 256];
    outh[off + tid]       = __float2half_rn(y0);
    outh[off + tid + 256] = __float2half_rn(y1);
}

// ---------------------------------------------------------------------------
// Fused residual + LayerNorm2 -> output (out1 read as fp16)
// ---------------------------------------------------------------------------
__global__ void __launch_bounds__(256) resid_ln_kernel(
    const __half* __restrict__ a, const float* __restrict__ f,
    const float* __restrict__ gamma, const float* __restrict__ beta,
    float* __restrict__ out)
{
    const int row = blockIdx.x;
    const int tid = threadIdx.x;
    const int lane = tid & 31, wid = tid >> 5;
    const size_t off = (size_t)row * DD;

    float r0 = __half2float(a[off + tid])       + f[off + tid];
    float r1 = __half2float(a[off + tid + 256]) + f[off + tid + 256];

    float s = warp_sum(r0 + r1);
    float ss = warp_sum(r0 * r0 + r1 * r1);
    __shared__ float rs[8], rss[8];
    if (lane == 0) { rs[wid] = s; rss[wid] = ss; }
    __syncthreads();
    __shared__ float mv[2];
    if (tid == 0) {
        float S = 0.f, SS = 0.f;
#pragma unroll
        for (int i = 0; i < 8; i++) { S += rs[i]; SS += rss[i]; }
        float mean = S * (1.f / 512.f);
        float var = SS * (1.f / 512.f) - mean * mean;
        mv[0] = mean; mv[1] = rsqrtf(var + EPS);
    }
    __syncthreads();
    const float mean = mv[0], inv = mv[1];
    out[off + tid]       = (r0 - mean) * inv * gamma[tid]       + beta[tid];
    out[off + tid + 256] = (r1 - mean) * inv * gamma[tid + 256] + beta[tid + 256];
}

// ---------------------------------------------------------------------------
// Launch (prologue forked across streams; capture-safe fork/join via events)
// ---------------------------------------------------------------------------
extern "C" void kernel_launch(void* const* d_in, const int* in_sizes, int n_in,
                              void* d_out, int out_size)
{
    const float* query  = (const float*)d_in[0];
    const float* key    = (const float*)d_in[1];
    const float* value  = (const float*)d_in[2];
    const float* w_q    = (const float*)d_in[3];
    const float* b_q    = (const float*)d_in[4];
    const float* w_k    = (const float*)d_in[5];
    const float* b_k    = (const float*)d_in[6];
    const float* w_v    = (const float*)d_in[7];
    const float* b_v    = (const float*)d_in[8];
    const float* ln1_g  = (const float*)d_in[9];
    const float* ln1_b  = (const float*)d_in[10];
    const float* ln2_g  = (const float*)d_in[11];
    const float* ln2_b  = (const float*)d_in[12];
    const float* ffn_w1 = (const float*)d_in[13];
    const float* ffn_b1 = (const float*)d_in[14];
    const float* ffn_w2 = (const float*)d_in[15];
    const float* ffn_b2 = (const float*)d_in[16];
    float* out = (float*)d_out;

    void* sp = nullptr;
    cudaGetSymbolAddress(&sp, g_scratch);
    float* s = (float*)sp;
    float* g_ao   = s + F_AO;
    float* g_ffn  = s + F_FF;
    float* g_wp   = s + F_WP;
    float* g_sw   = s + F_SW;

    void* ap = nullptr;
    cudaGetSymbolAddress(&ap, g_act);
    __half* a = (__half*)ap;
    __half* qh  = a + B_QH;
    __half* kh  = a + B_KH;
    __half* vh  = a + B_VH;
    __half* o1h = a + B_O1H;
    __half* hh  = a + B_HH;
    __half* qph = a + B_QPH;

    void* wp = nullptr;
    cudaGetSymbolAddress(&wp, g_wsplit);
    __half* w = (__half*)wp;
    const size_t WSZ = 512u * 512u;
    __half* wqh = w + 0 * WSZ;
    __half* wkh = w + 1 * WSZ;
    __half* wvh = w + 2 * WSZ;
    __half* f1h = w + 3 * WSZ;
    __half* f2h = w + 4 * WSZ;

    cudaFuncSetAttribute((const void*)gemm_h<true,  true,  false, false, true >, cudaFuncAttributeMaxDynamicSharedMemorySize, GEMM_SMEM);
    cudaFuncSetAttribute((const void*)gemm_h<true,  false, false, true,  true >, cudaFuncAttributeMaxDynamicSharedMemorySize, GEMM_SMEM);
    cudaFuncSetAttribute((const void*)gemm_h<false, false, true,  false, false>, cudaFuncAttributeMaxDynamicSharedMemorySize, GEMM_SMEM);
    cudaFuncSetAttribute((const void*)gemm_h<false, false, true,  false, true >, cudaFuncAttributeMaxDynamicSharedMemorySize, GEMM_SMEM);

    // side streams + events (created once, before any capture; reused since)
    static cudaStream_t s1 = nullptr, s2 = nullptr;
    static cudaEvent_t e0 = nullptr, e1 = nullptr, e2 = nullptr;
    if (s1 == nullptr) {
        cudaStreamCreateWithFlags(&s1, cudaStreamNonBlocking);
        cudaStreamCreateWithFlags(&s2, cudaStreamNonBlocking);
        cudaEventCreateWithFlags(&e0, cudaEventDisableTiming);
        cudaEventCreateWithFlags(&e1, cudaEventDisableTiming);
        cudaEventCreateWithFlags(&e2, cudaEventDisableTiming);
    }

    const dim3 blk(256);
    const dim3 grid_q(DD / 128, NQ / 128);   // 4 x 64
    const dim3 grid_kv(DD / 128, NKV / 128); // 4 x 256

    // fork: prep (main) || q convert (s1) || key convert (s2)
    cudaEventRecord(e0, 0);
    cudaStreamWaitEvent(s1, e0, 0);
    cudaStreamWaitEvent(s2, e0, 0);

    prep_weight5<<<dim3(16, 16, 5), dim3(32, 8)>>>(w_q, w_k, w_v, ffn_w1, ffn_w2, w);
    f32_to_h<<<NQ  * DD / 1024, blk, 0, s1>>>((const float4*)query, (uint2*)qh);
    f32_to_h<<<NKV * DD / 1024, blk, 0, s2>>>((const float4*)key,   (uint2*)kh);

    cudaEventRecord(e1, s1);
    cudaEventRecord(e2, s2);

    // Q projection (needs prep + qh): fp16 q only
    cudaStreamWaitEvent(0, e1, 0);
    gemm_h<true, true, false, false, true><<<grid_q, blk, GEMM_SMEM>>>(
        qh, wqh, b_q, nullptr, qph, nullptr, nullptr);

    // K projection with fused q.k dot (needs kh + qph)
    cudaStreamWaitEvent(0, e2, 0);
    gemm_h<true, false, false, true, true><<<grid_kv, blk, GEMM_SMEM>>>(
        kh, wkh, b_k, nullptr, nullptr, qph, g_wp);

    // downsample raw value by w
    wds_kernel<<<NQ, blk>>>(g_wp, value, vh, g_sw);

    // V projection on downsampled rows
    gemm_h<false, false, true, false, false><<<grid_q, blk, GEMM_SMEM>>>(
        vh, wvh, nullptr, g_ao, nullptr, nullptr, nullptr);

    // LN1 (fp16 q + fp32 ao) -> fp16 out1
    attn_ln_kernel<<<NQ, blk>>>(qph, g_ao, g_sw, b_v, ln1_g, ln1_b, o1h);

    // FFN
    gemm_h<true, true, false, false, true><<<grid_q, blk, GEMM_SMEM>>>(
        o1h, f1h, ffn_b1, nullptr, hh, nullptr, nullptr);
    gemm_h<false, false, true, false, true><<<grid_q, blk, GEMM_SMEM>>>(
        hh, f2h, ffn_b2, g_ffn, nullptr, nullptr, nullptr);

    resid_ln_kernel<<<NQ, blk>>>(o1h, g_ffn, ln2_g, ln2_b, out);
}